// round 1
// baseline (speedup 1.0000x reference)
#include <cuda_runtime.h>
#include <math.h>

#define NN 150000
#define EE 2400000
#define BBG 50000          // batch/graphs
#define HF 128
#define HF2 64

// ---------------- scratch (static device globals; no allocation) -------------
__device__ float g_bufA[(size_t)NN * HF];   // 76.8 MB
__device__ float g_bufB[(size_t)NN * HF];   // 76.8 MB
__device__ float g_dinv[NN];
__device__ int   g_deg[NN];
__device__ int   g_rowptr[NN + 1];
__device__ int   g_cursor[NN];
__device__ int   g_colsrc[EE];

// ---------------- setup kernels ---------------------------------------------
__global__ void k_zero_deg() {
    int i = blockIdx.x * blockDim.x + threadIdx.x;
    if (i < NN) g_deg[i] = 0;
}

__global__ void k_count(const int* __restrict__ ei) {
    int e = blockIdx.x * blockDim.x + threadIdx.x;
    if (e < EE) atomicAdd(&g_deg[ei[EE + e]], 1);   // dst half
}

// one block, 1024 threads: exclusive scan of deg -> rowptr, cursor, dinv
__global__ void k_scan() {
    __shared__ int s[1024];
    const int t = threadIdx.x;
    const int chunk = (NN + 1023) / 1024;
    const int start = t * chunk;
    const int end = min(start + chunk, NN);
    int sum = 0;
    for (int i = start; i < end; i++) sum += g_deg[i];
    s[t] = sum;
    __syncthreads();
    // Hillis-Steele inclusive scan
    for (int off = 1; off < 1024; off <<= 1) {
        int v = (t >= off) ? s[t - off] : 0;
        __syncthreads();
        s[t] += v;
        __syncthreads();
    }
    if (t == 0) g_rowptr[NN] = s[1023];
    int base = (t == 0) ? 0 : s[t - 1];
    for (int i = start; i < end; i++) {
        g_rowptr[i] = base;
        g_cursor[i] = base;
        int d = g_deg[i];
        base += d;
        g_dinv[i] = rsqrtf((float)(d + 1));  // self-loop in degree
    }
}

__global__ void k_scatter(const int* __restrict__ ei) {
    int e = blockIdx.x * blockDim.x + threadIdx.x;
    if (e < EE) {
        int srcn = ei[e];
        int dstn = ei[EE + e];
        int pos = atomicAdd(&g_cursor[dstn], 1);
        g_colsrc[pos] = srcn;
    }
}

// ---------------- SGEMM: C[M,N] = A[M,K] @ W[K,N] (+bias,relu) ---------------
// BM=128, BN=64, BK=16, 256 threads, TM=8, TN=4
#define BM 128
#define BN 64
#define BK 16

template <bool FUSE>
__global__ void __launch_bounds__(256)
k_sgemm(const float* __restrict__ A, const float* __restrict__ W,
        const float* __restrict__ bias, float* __restrict__ C,
        int M, int K, int N) {
    __shared__ float As[BK][BM + 4];
    __shared__ float Bs[BK][BN];
    const int tid = threadIdx.x;
    const int tx = tid & 15;    // col group (4 cols)
    const int ty = tid >> 4;    // row group (8 rows)
    const int bm = blockIdx.y * BM;
    const int bn = blockIdx.x * BN;

    const int arow = tid >> 2;        // 0..63
    const int acol = (tid & 3) * 4;   // 0,4,8,12
    const int brow = tid >> 4;        // 0..15
    const int bcol = (tid & 15) * 4;

    float acc[8][4];
#pragma unroll
    for (int i = 0; i < 8; i++)
#pragma unroll
        for (int j = 0; j < 4; j++) acc[i][j] = 0.f;

    for (int k0 = 0; k0 < K; k0 += BK) {
#pragma unroll
        for (int h = 0; h < 2; h++) {
            int r = arow + h * 64;
            int gr = bm + r;
            float4 a = make_float4(0.f, 0.f, 0.f, 0.f);
            if (gr < M) a = *(const float4*)&A[(size_t)gr * K + k0 + acol];
            As[acol + 0][r] = a.x;
            As[acol + 1][r] = a.y;
            As[acol + 2][r] = a.z;
            As[acol + 3][r] = a.w;
        }
        *(float4*)&Bs[brow][bcol] =
            *(const float4*)&W[(size_t)(k0 + brow) * N + bn + bcol];
        __syncthreads();
#pragma unroll
        for (int k = 0; k < BK; k++) {
            float4 a0 = *(const float4*)&As[k][ty * 8];
            float4 a1 = *(const float4*)&As[k][ty * 8 + 4];
            float4 b0 = *(const float4*)&Bs[k][tx * 4];
            float af[8] = {a0.x, a0.y, a0.z, a0.w, a1.x, a1.y, a1.z, a1.w};
            float bf[4] = {b0.x, b0.y, b0.z, b0.w};
#pragma unroll
            for (int i = 0; i < 8; i++)
#pragma unroll
                for (int j = 0; j < 4; j++) acc[i][j] += af[i] * bf[j];
        }
        __syncthreads();
    }

    float4 bv = make_float4(0.f, 0.f, 0.f, 0.f);
    if (FUSE) bv = *(const float4*)&bias[bn + tx * 4];
#pragma unroll
    for (int i = 0; i < 8; i++) {
        int gr = bm + ty * 8 + i;
        if (gr >= M) continue;
        float4 o = make_float4(acc[i][0], acc[i][1], acc[i][2], acc[i][3]);
        if (FUSE) {
            o.x = fmaxf(o.x + bv.x, 0.f);
            o.y = fmaxf(o.y + bv.y, 0.f);
            o.z = fmaxf(o.z + bv.z, 0.f);
            o.w = fmaxf(o.w + bv.w, 0.f);
        }
        *(float4*)&C[(size_t)gr * N + bn + tx * 4] = o;
    }
}

// ---------------- gather-based GCN aggregation (warp per node) ---------------
// out[i] = relu( bias + dinv_i^2 * h[i] + sum_{e: dst=i} dinv[src]*dinv_i * h[src] )
template <int F>
__global__ void k_agg(const float* __restrict__ h, const float* __restrict__ bias,
                      float* __restrict__ out) {
    int warp = (blockIdx.x * blockDim.x + threadIdx.x) >> 5;
    int lane = threadIdx.x & 31;
    if (warp >= NN) return;
    const int VPL = F / 32;  // 4 (F=128) or 2 (F=64)
    float di = g_dinv[warp];
    float di2 = di * di;
    float acc[VPL];
    const float* hrow = h + (size_t)warp * F + lane * VPL;
    if (VPL == 4) {
        float4 v = *(const float4*)hrow;
        acc[0] = v.x * di2; acc[1] = v.y * di2; acc[2] = v.z * di2; acc[3] = v.w * di2;
    } else {
        float2 v = *(const float2*)hrow;
        acc[0] = v.x * di2; acc[1] = v.y * di2;
    }
    int beg = g_rowptr[warp];
    int end = g_rowptr[warp + 1];
    for (int j = beg; j < end; j++) {
        int s = g_colsrc[j];
        float w = g_dinv[s] * di;
        const float* hs = h + (size_t)s * F + lane * VPL;
        if (VPL == 4) {
            float4 v = *(const float4*)hs;
            acc[0] += v.x * w; acc[1] += v.y * w; acc[2] += v.z * w; acc[3] += v.w * w;
        } else {
            float2 v = *(const float2*)hs;
            acc[0] += v.x * w; acc[1] += v.y * w;
        }
    }
    float* orow = out + (size_t)warp * F + lane * VPL;
    if (VPL == 4) {
        float4 b = *(const float4*)&bias[lane * 4];
        float4 o;
        o.x = fmaxf(acc[0] + b.x, 0.f);
        o.y = fmaxf(acc[1] + b.y, 0.f);
        o.z = fmaxf(acc[2] + b.z, 0.f);
        o.w = fmaxf(acc[3] + b.w, 0.f);
        *(float4*)orow = o;
    } else {
        float2 b = *(const float2*)&bias[lane * 2];
        float2 o;
        o.x = fmaxf(acc[0] + b.x, 0.f);
        o.y = fmaxf(acc[1] + b.y, 0.f);
        *(float2*)orow = o;
    }
}

// ---------------- final 64->2 + log_softmax ----------------------------------
__global__ void k_final(const float* __restrict__ z, const float* __restrict__ Wc3,
                        const float* __restrict__ bc3, float* __restrict__ out) {
    __shared__ float sw[HF2 * 2];
    __shared__ float sb[2];
    if (threadIdx.x < HF2 * 2) sw[threadIdx.x] = Wc3[threadIdx.x];
    if (threadIdx.x < 2) sb[threadIdx.x] = bc3[threadIdx.x];
    __syncthreads();
    int g = blockIdx.x * blockDim.x + threadIdx.x;
    if (g >= BBG) return;
    const float* zr = z + (size_t)g * HF2;
    float a0 = sb[0], a1 = sb[1];
#pragma unroll
    for (int k = 0; k < HF2; k++) {
        float zv = zr[k];
        a0 += zv * sw[2 * k + 0];
        a1 += zv * sw[2 * k + 1];
    }
    float m = fmaxf(a0, a1);
    float l = logf(expf(a0 - m) + expf(a1 - m));
    out[2 * g + 0] = a0 - m - l;
    out[2 * g + 1] = a1 - m - l;
}

// ---------------- launch -----------------------------------------------------
extern "C" void kernel_launch(void* const* d_in, const int* in_sizes, int n_in,
                              void* d_out, int out_size) {
    const float* x   = (const float*)d_in[0];
    const int*   ei  = (const int*)d_in[1];
    const float* W1  = (const float*)d_in[2];
    const float* b1  = (const float*)d_in[3];
    const float* W2  = (const float*)d_in[4];
    const float* b2  = (const float*)d_in[5];
    const float* W3  = (const float*)d_in[6];
    const float* b3  = (const float*)d_in[7];
    const float* Wc1 = (const float*)d_in[8];
    const float* bc1 = (const float*)d_in[9];
    const float* Wc2 = (const float*)d_in[10];
    const float* bc2 = (const float*)d_in[11];
    const float* Wc3 = (const float*)d_in[12];
    const float* bc3 = (const float*)d_in[13];
    float* out = (float*)d_out;

    float* bufA;
    float* bufB;
    cudaGetSymbolAddress((void**)&bufA, g_bufA);
    cudaGetSymbolAddress((void**)&bufB, g_bufB);

    // --- graph preprocessing: degrees, dinv, CSR by dst ---
    k_zero_deg<<<(NN + 255) / 256, 256>>>();
    k_count<<<(EE + 255) / 256, 256>>>(ei);
    k_scan<<<1, 1024>>>();
    k_scatter<<<(EE + 255) / 256, 256>>>(ei);

    const int aggBlocks = (NN * 32 + 255) / 256;
    dim3 g1(HF / BN, (NN + BM - 1) / BM);    // N=128
    dim3 g3(HF2 / BN, (NN + BM - 1) / BM);   // N=64
    dim3 gc1(HF / BN, (BBG + BM - 1) / BM);  // 50000 x 128
    dim3 gc2(HF2 / BN, (BBG + BM - 1) / BM); // 50000 x 64

    // layer 1
    k_sgemm<false><<<g1, 256>>>(x, W1, nullptr, bufA, NN, HF, HF);
    k_agg<HF><<<aggBlocks, 256>>>(bufA, b1, bufB);
    // layer 2
    k_sgemm<false><<<g1, 256>>>(bufB, W2, nullptr, bufA, NN, HF, HF);
    k_agg<HF><<<aggBlocks, 256>>>(bufA, b2, bufB);
    // layer 3 (128 -> 64)
    k_sgemm<false><<<g3, 256>>>(bufB, W3, nullptr, bufA, NN, HF, HF2);
    k_agg<HF2><<<aggBlocks, 256>>>(bufA, b3, bufB);
    // classifier: bufB viewed as [50000, 192]
    k_sgemm<true><<<gc1, 256>>>(bufB, Wc1, bc1, bufA, BBG, 3 * HF2, HF);
    k_sgemm<true><<<gc2, 256>>>(bufA, Wc2, bc2, bufB, BBG, HF, HF2);
    // final 64->2 + log_softmax
    k_final<<<(BBG + 255) / 256, 256>>>(bufB, Wc3, bc3, out);
}

// round 3
// speedup vs baseline: 1.1559x; 1.1559x over previous
#include <cuda_runtime.h>
#include <cuda_bf16.h>
#include <stdint.h>
#include <math.h>

#define NN 150000
#define EE 2400000
#define BBG 50000
#define HF 128
#define HF2 64

// ---------------- scratch (static device globals; no allocation) -------------
__device__ float g_bufA[(size_t)NN * HF];
__device__ float g_bufB[(size_t)NN * HF];
__device__ float g_dinv[NN];
__device__ int   g_deg[NN];
__device__ int   g_rowptr[NN + 1];
__device__ int   g_cursor[NN];
__device__ int   g_colsrc[EE];

// ---------------- setup kernels ---------------------------------------------
__global__ void k_zero_deg() {
    int i = blockIdx.x * blockDim.x + threadIdx.x;
    if (i < NN) g_deg[i] = 0;
}

__global__ void k_count(const int* __restrict__ ei) {
    int e = blockIdx.x * blockDim.x + threadIdx.x;
    if (e < EE) atomicAdd(&g_deg[ei[EE + e]], 1);
}

__global__ void k_scan() {
    __shared__ int s[1024];
    const int t = threadIdx.x;
    const int chunk = (NN + 1023) / 1024;
    const int start = t * chunk;
    const int end = min(start + chunk, NN);
    int sum = 0;
    for (int i = start; i < end; i++) sum += g_deg[i];
    s[t] = sum;
    __syncthreads();
    for (int off = 1; off < 1024; off <<= 1) {
        int v = (t >= off) ? s[t - off] : 0;
        __syncthreads();
        s[t] += v;
        __syncthreads();
    }
    if (t == 0) g_rowptr[NN] = s[1023];
    int base = (t == 0) ? 0 : s[t - 1];
    for (int i = start; i < end; i++) {
        g_rowptr[i] = base;
        g_cursor[i] = base;
        int d = g_deg[i];
        base += d;
        g_dinv[i] = rsqrtf((float)(d + 1));
    }
}

__global__ void k_scatter(const int* __restrict__ ei) {
    int e = blockIdx.x * blockDim.x + threadIdx.x;
    if (e < EE) {
        int srcn = ei[e];
        int dstn = ei[EE + e];
        int pos = atomicAdd(&g_cursor[dstn], 1);
        g_colsrc[pos] = srcn;
    }
}

// ---------------- bf16 split-MMA GEMM ---------------------------------------
// C[M,N] = A[M,K] @ W[K,N] (+bias,relu). fp32 in/out.
// bf16 hi/lo split, 3 mma products (AhBh + AhBl + AlBh). Error ~2^-17.
// Block tile 128x64 (8 warps, warp tile 32x32), BK=32.

#define BM 128
#define BN 64
#define BK 32
#define SA 20   // As pair-stride (bf162 units)
#define SB 72   // Bs row-stride (bf162 units)

__device__ __forceinline__ void split2(float x, float y, uint32_t& hi, uint32_t& lo) {
    __nv_bfloat16 hx = __float2bfloat16(x);
    __nv_bfloat16 hy = __float2bfloat16(y);
    float rx = x - __bfloat162float(hx);
    float ry = y - __bfloat162float(hy);
    __nv_bfloat162 h;
    h.x = hx; h.y = hy;
    __nv_bfloat162 l = __floats2bfloat162_rn(rx, ry);
    hi = reinterpret_cast<uint32_t&>(h);
    lo = reinterpret_cast<uint32_t&>(l);
}

__device__ __forceinline__ void mma16816(float c[4], const uint32_t a[4], const uint32_t b[2]) {
    asm volatile(
        "mma.sync.aligned.m16n8k16.row.col.f32.bf16.bf16.f32 "
        "{%0,%1,%2,%3}, {%4,%5,%6,%7}, {%8,%9}, {%0,%1,%2,%3};"
        : "+f"(c[0]), "+f"(c[1]), "+f"(c[2]), "+f"(c[3])
        : "r"(a[0]), "r"(a[1]), "r"(a[2]), "r"(a[3]), "r"(b[0]), "r"(b[1]));
}

template <bool FUSE>
__global__ void __launch_bounds__(256)
k_mma(const float* __restrict__ A, const float* __restrict__ W,
      const float* __restrict__ bias, float* __restrict__ C,
      int M, int K, int N) {
    __shared__ uint32_t sAh[BM * SA];
    __shared__ uint32_t sAl[BM * SA];
    __shared__ uint32_t sBh[(BK / 2) * SB];
    __shared__ uint32_t sBl[(BK / 2) * SB];

    const int tid = threadIdx.x;
    const int wid = tid >> 5;
    const int lane = tid & 31;
    const int wm = wid & 3;     // warp row (32 rows each)
    const int wn = wid >> 2;    // warp col (32 cols each)
    const int gid = lane >> 2;
    const int tig = lane & 3;
    const int bm = blockIdx.y * BM;
    const int bn = blockIdx.x * BN;

    float c[8][4];
#pragma unroll
    for (int i = 0; i < 8; i++)
#pragma unroll
        for (int j = 0; j < 4; j++) c[i][j] = 0.f;

    const int bkk = tid >> 4;
    const int bn0 = (tid & 15) * 4;

    for (int k0 = 0; k0 < K; k0 += BK) {
        // --- A tile: 128 rows x 32 cols fp32 -> hi/lo bf162 pairs ---
#pragma unroll
        for (int i = 0; i < 4; i++) {
            int task = tid + i * 256;
            int row = task >> 3;
            int cg = task & 7;
            float4 v = make_float4(0.f, 0.f, 0.f, 0.f);
            int gr = bm + row;
            if (gr < M) v = *(const float4*)&A[(size_t)gr * K + k0 + cg * 4];
            uint32_t h0, l0, h1, l1;
            split2(v.x, v.y, h0, l0);
            split2(v.z, v.w, h1, l1);
            int base = row * SA + cg * 2;
            sAh[base] = h0;     sAl[base] = l0;
            sAh[base + 1] = h1; sAl[base + 1] = l1;
        }
        // --- B tile: 32 rows x 64 cols fp32 -> pair (k even, k odd) bf162 ---
        {
            int gk = k0 + 2 * bkk;
            float4 u = *(const float4*)&W[(size_t)gk * N + bn + bn0];
            float4 w = *(const float4*)&W[(size_t)(gk + 1) * N + bn + bn0];
            float ue[4] = {u.x, u.y, u.z, u.w};
            float we[4] = {w.x, w.y, w.z, w.w};
#pragma unroll
            for (int j = 0; j < 4; j++) {
                uint32_t h, l;
                split2(ue[j], we[j], h, l);
                sBh[bkk * SB + bn0 + j] = h;
                sBl[bkk * SB + bn0 + j] = l;
            }
        }
        __syncthreads();

#pragma unroll
        for (int ks = 0; ks < 2; ks++) {
            const int p0 = ks * 8;
            uint32_t ah[2][4], al[2][4];
#pragma unroll
            for (int mt = 0; mt < 2; mt++) {
                int r = wm * 32 + mt * 16 + gid;
                int b0 = r * SA + p0 + tig;
                ah[mt][0] = sAh[b0];
                ah[mt][1] = sAh[b0 + 8 * SA];
                ah[mt][2] = sAh[b0 + 4];
                ah[mt][3] = sAh[b0 + 8 * SA + 4];
                al[mt][0] = sAl[b0];
                al[mt][1] = sAl[b0 + 8 * SA];
                al[mt][2] = sAl[b0 + 4];
                al[mt][3] = sAl[b0 + 8 * SA + 4];
            }
            uint32_t bh[4][2], bl[4][2];
#pragma unroll
            for (int nt = 0; nt < 4; nt++) {
                int cc = wn * 32 + nt * 8 + gid;
                bh[nt][0] = sBh[(p0 + tig) * SB + cc];
                bh[nt][1] = sBh[(p0 + tig + 4) * SB + cc];
                bl[nt][0] = sBl[(p0 + tig) * SB + cc];
                bl[nt][1] = sBl[(p0 + tig + 4) * SB + cc];
            }
#pragma unroll
            for (int mt = 0; mt < 2; mt++)
#pragma unroll
                for (int nt = 0; nt < 4; nt++) {
                    int t = mt * 4 + nt;
                    mma16816(c[t], ah[mt], bh[nt]);
                    mma16816(c[t], ah[mt], bl[nt]);
                    mma16816(c[t], al[mt], bh[nt]);
                }
        }
        __syncthreads();
    }

    // --- epilogue ---
#pragma unroll
    for (int mt = 0; mt < 2; mt++)
#pragma unroll
        for (int nt = 0; nt < 4; nt++) {
            int t = mt * 4 + nt;
            int gr0 = bm + wm * 32 + mt * 16 + gid;
            int gc = bn + wn * 32 + nt * 8 + tig * 2;
            float v0 = c[t][0], v1 = c[t][1], v2 = c[t][2], v3 = c[t][3];
            if (FUSE) {
                float b0 = bias[gc], b1 = bias[gc + 1];
                v0 = fmaxf(v0 + b0, 0.f);
                v1 = fmaxf(v1 + b1, 0.f);
                v2 = fmaxf(v2 + b0, 0.f);
                v3 = fmaxf(v3 + b1, 0.f);
            }
            if (gr0 < M) *(float2*)&C[(size_t)gr0 * N + gc] = make_float2(v0, v1);
            if (gr0 + 8 < M) *(float2*)&C[(size_t)(gr0 + 8) * N + gc] = make_float2(v2, v3);
        }
}

// ---------------- gather-based GCN aggregation (warp per node) ---------------
template <int F>
__global__ void k_agg(const float* __restrict__ h, const float* __restrict__ bias,
                      float* __restrict__ out) {
    int warp = (blockIdx.x * blockDim.x + threadIdx.x) >> 5;
    int lane = threadIdx.x & 31;
    if (warp >= NN) return;
    const int VPL = F / 32;
    float di = g_dinv[warp];
    float di2 = di * di;
    float acc[VPL];
    const float* hrow = h + (size_t)warp * F + lane * VPL;
    if (VPL == 4) {
        float4 v = *(const float4*)hrow;
        acc[0] = v.x * di2; acc[1] = v.y * di2; acc[2] = v.z * di2; acc[3] = v.w * di2;
    } else {
        float2 v = *(const float2*)hrow;
        acc[0] = v.x * di2; acc[1] = v.y * di2;
    }
    int beg = g_rowptr[warp];
    int end = g_rowptr[warp + 1];
    for (int j = beg; j < end; j++) {
        int s = g_colsrc[j];
        float w = g_dinv[s] * di;
        const float* hs = h + (size_t)s * F + lane * VPL;
        if (VPL == 4) {
            float4 v = *(const float4*)hs;
            acc[0] += v.x * w; acc[1] += v.y * w; acc[2] += v.z * w; acc[3] += v.w * w;
        } else {
            float2 v = *(const float2*)hs;
            acc[0] += v.x * w; acc[1] += v.y * w;
        }
    }
    float* orow = out + (size_t)warp * F + lane * VPL;
    if (VPL == 4) {
        float4 b = *(const float4*)&bias[lane * 4];
        float4 o;
        o.x = fmaxf(acc[0] + b.x, 0.f);
        o.y = fmaxf(acc[1] + b.y, 0.f);
        o.z = fmaxf(acc[2] + b.z, 0.f);
        o.w = fmaxf(acc[3] + b.w, 0.f);
        *(float4*)orow = o;
    } else {
        float2 b = *(const float2*)&bias[lane * 2];
        float2 o;
        o.x = fmaxf(acc[0] + b.x, 0.f);
        o.y = fmaxf(acc[1] + b.y, 0.f);
        *(float2*)orow = o;
    }
}

// ---------------- final 64->2 + log_softmax ----------------------------------
__global__ void k_final(const float* __restrict__ z, const float* __restrict__ Wc3,
                        const float* __restrict__ bc3, float* __restrict__ out) {
    __shared__ float sw[HF2 * 2];
    __shared__ float sb[2];
    if (threadIdx.x < HF2 * 2) sw[threadIdx.x] = Wc3[threadIdx.x];
    if (threadIdx.x < 2) sb[threadIdx.x] = bc3[threadIdx.x];
    __syncthreads();
    int g = blockIdx.x * blockDim.x + threadIdx.x;
    if (g >= BBG) return;
    const float* zr = z + (size_t)g * HF2;
    float a0 = sb[0], a1 = sb[1];
#pragma unroll
    for (int k = 0; k < HF2; k++) {
        float zv = zr[k];
        a0 += zv * sw[2 * k + 0];
        a1 += zv * sw[2 * k + 1];
    }
    float m = fmaxf(a0, a1);
    float l = logf(expf(a0 - m) + expf(a1 - m));
    out[2 * g + 0] = a0 - m - l;
    out[2 * g + 1] = a1 - m - l;
}

// ---------------- launch -----------------------------------------------------
extern "C" void kernel_launch(void* const* d_in, const int* in_sizes, int n_in,
                              void* d_out, int out_size) {
    const float* x   = (const float*)d_in[0];
    const int*   ei  = (const int*)d_in[1];
    const float* W1  = (const float*)d_in[2];
    const float* b1  = (const float*)d_in[3];
    const float* W2  = (const float*)d_in[4];
    const float* b2  = (const float*)d_in[5];
    const float* W3  = (const float*)d_in[6];
    const float* b3  = (const float*)d_in[7];
    const float* Wc1 = (const float*)d_in[8];
    const float* bc1 = (const float*)d_in[9];
    const float* Wc2 = (const float*)d_in[10];
    const float* bc2 = (const float*)d_in[11];
    const float* Wc3 = (const float*)d_in[12];
    const float* bc3 = (const float*)d_in[13];
    float* out = (float*)d_out;

    float* bufA;
    float* bufB;
    cudaGetSymbolAddress((void**)&bufA, g_bufA);
    cudaGetSymbolAddress((void**)&bufB, g_bufB);

    // --- graph preprocessing ---
    k_zero_deg<<<(NN + 255) / 256, 256>>>();
    k_count<<<(EE + 255) / 256, 256>>>(ei);
    k_scan<<<1, 1024>>>();
    k_scatter<<<(EE + 255) / 256, 256>>>(ei);

    const int aggBlocks = (NN * 32 + 255) / 256;
    const int mRows = (NN + BM - 1) / BM;
    const int cRows = (BBG + BM - 1) / BM;
    dim3 g1(HF / BN, mRows);     // N=128
    dim3 g3(HF2 / BN, mRows);    // N=64
    dim3 gc1(HF / BN, cRows);
    dim3 gc2(HF2 / BN, cRows);

    // layer 1
    k_mma<false><<<g1, 256>>>(x, W1, nullptr, bufA, NN, HF, HF);
    k_agg<HF><<<aggBlocks, 256>>>(bufA, b1, bufB);
    // layer 2
    k_mma<false><<<g1, 256>>>(bufB, W2, nullptr, bufA, NN, HF, HF);
    k_agg<HF><<<aggBlocks, 256>>>(bufA, b2, bufB);
    // layer 3 (128 -> 64)
    k_mma<false><<<g3, 256>>>(bufB, W3, nullptr, bufA, NN, HF, HF2);
    k_agg<HF2><<<aggBlocks, 256>>>(bufA, b3, bufB);
    // classifier
    k_mma<true><<<gc1, 256>>>(bufB, Wc1, bc1, bufA, BBG, 3 * HF2, HF);
    k_mma<true><<<gc2, 256>>>(bufA, Wc2, bc2, bufB, BBG, HF, HF2);
    // final 64->2 + log_softmax
    k_final<<<(BBG + 255) / 256, 256>>>(bufB, Wc3, bc3, out);
}